// round 4
// baseline (speedup 1.0000x reference)
#include <cuda_runtime.h>
#include <math.h>

#define EPSF 1e-7f
#define MAX_TANHF (1.0f - 1e-6f)

constexpr int F = 128;
constexpr int NMAX = 8192;

__device__ float g_V [NMAX * F];      // log0(h)
__device__ float g_C [NMAX * 2 * F];  // log0([x ; neigh])

typedef unsigned long long ull;

__device__ __forceinline__ float warp_sum(float v) {
    v += __shfl_xor_sync(0xffffffffu, v, 16);
    v += __shfl_xor_sync(0xffffffffu, v, 8);
    v += __shfl_xor_sync(0xffffffffu, v, 4);
    v += __shfl_xor_sync(0xffffffffu, v, 2);
    v += __shfl_xor_sync(0xffffffffu, v, 1);
    return v;
}

__device__ __forceinline__ float dot4(float4 a, float4 b) {
    return a.x * b.x + a.y * b.y + a.z * b.z + a.w * b.w;
}

__device__ __forceinline__ void ffma2(ull& d, ull a, ull b) {
    asm("fma.rn.f32x2 %0, %1, %2, %0;" : "+l"(d) : "l"(a), "l"(b));
}
__device__ __forceinline__ ull pack2(float lo, float hi) {
    ull r; asm("mov.b64 %0, {%1, %2};" : "=l"(r) : "f"(lo), "f"(hi)); return r;
}
__device__ __forceinline__ float2 unpack2(ull v) {
    float2 r; asm("mov.b64 {%0, %1}, %2;" : "=f"(r.x), "=f"(r.y) : "l"(v)); return r;
}

// GEMM geometry: 64-row tile, 256 threads (8 warps).
// Thread: 8 rows (4 row-pairs) x 4 cols -> 32 MACs = 16 FFMA2 per k.
// A transposed+packed in smem: Ap[k*SA + pair], 32 pairs per tile.
constexpr int SA = 33;                       // 32 pairs + 1 pad (ull units)
constexpr int BS_BYTES = 128 * 128 * 4;      // 64 KB (one K-chunk of B)
constexpr int AP_BYTES = 128 * SA * 8;       // 33792 B
constexpr int SMEM_G = BS_BYTES + AP_BYTES + 512;

// Epilogue shared by both GEMMs: exp0 -> h_add(bias) [-> log0 if DO_LOG].
// Warp handles its 8 rows; each lane holds 4 cols of each row.
template <bool DO_LOG>
__device__ __forceinline__ void gemm_epilogue(
        ull acc[4][4], const float* __restrict__ bias,
        float* __restrict__ Out, int row0, int w, int lane) {
    int c4 = lane * 4;
    float4 bb = *(const float4*)(bias + c4);
    float y2 = warp_sum(dot4(bb, bb));
    float4* O4 = (float4*)Out;
#pragma unroll
    for (int p = 0; p < 4; p++) {
        float2 u0 = unpack2(acc[p][0]), u1 = unpack2(acc[p][1]);
        float2 u2 = unpack2(acc[p][2]), u3 = unpack2(acc[p][3]);
        float4 ur[2] = {make_float4(u0.x, u1.x, u2.x, u3.x),
                        make_float4(u0.y, u1.y, u2.y, u3.y)};
#pragma unroll
        for (int q = 0; q < 2; q++) {
            float4 u = ur[q];
            int row = row0 + w * 8 + 2 * p + q;
            float ne2 = warp_sum(dot4(u, u));
            float ne = fmaxf(sqrtf(ne2), EPSF);
            float sc = tanhf(ne) / ne;
            float4 h = make_float4(u.x * sc, u.y * sc, u.z * sc, u.w * sc);
            float xy = warp_sum(dot4(h, bb));
            float x2 = sc * sc * ne2;
            float c1 = 1.f + 2.f * xy + y2;
            float c2 = 1.f - x2;
            float inv_den = 1.f / fmaxf(1.f + 2.f * xy + x2 * y2, EPSF);
            float4 rr = make_float4((c1 * h.x + c2 * bb.x) * inv_den,
                                    (c1 * h.y + c2 * bb.y) * inv_den,
                                    (c1 * h.z + c2 * bb.z) * inv_den,
                                    (c1 * h.w + c2 * bb.w) * inv_den);
            if (DO_LOG) {
                float nr2 = warp_sum(dot4(rr, rr));
                float nr = fmaxf(sqrtf(nr2), EPSF);
                float s = atanhf(fminf(nr, MAX_TANHF)) / nr;
                rr = make_float4(rr.x * s, rr.y * s, rr.z * s, rr.w * s);
            }
            O4[(size_t)row * 32 + lane] = rr;
        }
    }
}

// FFMA2 mainloop over one 128-k chunk.
__device__ __forceinline__ void gemm_mainloop(
        const float* __restrict__ Bs, const ull* __restrict__ Ap,
        ull acc[4][4], int lane, int w) {
    int c4 = lane * 4;
    int pb = w * 4;  // 4 row-pairs per warp
#pragma unroll 4
    for (int k = 0; k < 128; k++) {
        float4 b4 = *(const float4*)(Bs + k * 128 + c4);
        ull bd0 = pack2(b4.x, b4.x), bd1 = pack2(b4.y, b4.y);
        ull bd2 = pack2(b4.z, b4.z), bd3 = pack2(b4.w, b4.w);
        const ull* ap = Ap + k * SA + pb;
        ull a0 = ap[0], a1 = ap[1], a2 = ap[2], a3 = ap[3];
        ffma2(acc[0][0], a0, bd0); ffma2(acc[0][1], a0, bd1);
        ffma2(acc[0][2], a0, bd2); ffma2(acc[0][3], a0, bd3);
        ffma2(acc[1][0], a1, bd0); ffma2(acc[1][1], a1, bd1);
        ffma2(acc[1][2], a1, bd2); ffma2(acc[1][3], a1, bd3);
        ffma2(acc[2][0], a2, bd0); ffma2(acc[2][1], a2, bd1);
        ffma2(acc[2][2], a2, bd2); ffma2(acc[2][3], a2, bd3);
        ffma2(acc[3][0], a3, bd0); ffma2(acc[3][1], a3, bd1);
        ffma2(acc[3][2], a3, bd2); ffma2(acc[3][3], a3, bd3);
    }
}

// ---------------------------------------------------------------------------
// Stage 1: V = log0( h_add( exp0( log0(x) @ embed ), ebias ) )
// ---------------------------------------------------------------------------
__global__ void __launch_bounds__(256)
k_g128(const float* __restrict__ x, const float* __restrict__ B,
       const float* __restrict__ ebias, float* __restrict__ V) {
    extern __shared__ char smraw[];
    float* Bs   = (float*)smraw;
    ull*   Ap   = (ull*)(smraw + BS_BYTES);
    float* srow = (float*)(smraw + BS_BYTES + AP_BYTES);

    int tid = threadIdx.x, lane = tid & 31, w = tid >> 5;
    int row0 = blockIdx.x * 64;
    const float4* X4 = (const float4*)x;

    // per-row log0 scales (warp w owns rows 8w..8w+7)
#pragma unroll
    for (int r = 0; r < 8; r++) {
        int row = w * 8 + r;
        float4 xv = X4[(size_t)(row0 + row) * 32 + lane];
        float n2 = warp_sum(dot4(xv, xv));
        float n = fmaxf(sqrtf(n2), EPSF);
        float sc = atanhf(fminf(n, MAX_TANHF)) / n;
        if (lane == 0) srow[row] = sc;
    }
    {
        const float4* B4 = (const float4*)B;
        float4* Bs4 = (float4*)Bs;
        for (int i = tid; i < 4096; i += 256) Bs4[i] = B4[i];
    }
    __syncthreads();

    // scaled transpose into row-pair-packed Ap (32 pairs x 128 k)
    for (int i = tid; i < 32 * 32; i += 256) {
        int pr = i >> 5, cg = i & 31;
        float s0 = srow[2 * pr], s1 = srow[2 * pr + 1];
        float4 v0 = X4[(size_t)(row0 + 2 * pr) * 32 + cg];
        float4 v1 = X4[(size_t)(row0 + 2 * pr + 1) * 32 + cg];
        Ap[(cg * 4 + 0) * SA + pr] = pack2(v0.x * s0, v1.x * s1);
        Ap[(cg * 4 + 1) * SA + pr] = pack2(v0.y * s0, v1.y * s1);
        Ap[(cg * 4 + 2) * SA + pr] = pack2(v0.z * s0, v1.z * s1);
        Ap[(cg * 4 + 3) * SA + pr] = pack2(v0.w * s0, v1.w * s1);
    }
    __syncthreads();

    ull acc[4][4];
#pragma unroll
    for (int p = 0; p < 4; p++)
#pragma unroll
        for (int c = 0; c < 4; c++) acc[p][c] = 0ull;

    gemm_mainloop(Bs, Ap, acc, lane, w);
    gemm_epilogue<true>(acc, ebias, V, row0, w, lane);
}

// ---------------------------------------------------------------------------
// Stage 2: C = log0([x ; exp0(adj @ V)]) — warp/row, branchless 2-deep stream
// ---------------------------------------------------------------------------
__global__ void k_spmm_fused(const float* __restrict__ adj,
                             const float* __restrict__ x, int N) {
    int warp = (blockIdx.x * blockDim.x + threadIdx.x) >> 5;
    int lane = threadIdx.x & 31;
    if (warp >= N) return;

    const float4* V4 = (const float4*)g_V;
    const float4* arow = (const float4*)(adj + (size_t)warp * N);
    float4 acc = make_float4(0.f, 0.f, 0.f, 0.f);

    int nq = N / 4;  // 2048
    float4 d0 = __ldcs(arow + lane);
    float4 d1 = __ldcs(arow + 32 + lane);

    for (int jb = 0; jb < nq; jb += 32) {
        float4 cur = d0;
        d0 = d1;
        int nx = jb + 64;
        nx = (nx > nq - 32) ? (nq - 32) : nx;  // clamp: branchless prefetch
        d1 = __ldcs(arow + nx + lane);
#pragma unroll
        for (int c = 0; c < 4; c++) {
            float av = (c == 0) ? cur.x : (c == 1) ? cur.y
                        : (c == 2) ? cur.z : cur.w;
            unsigned m = __ballot_sync(0xffffffffu, av != 0.0f);
            while (m) {
                int b = __ffs(m) - 1;
                m &= m - 1;
                float aval = __shfl_sync(0xffffffffu, av, b);
                int j = (jb + b) * 4 + c;
                float4 v = V4[(size_t)j * 32 + lane];
                acc.x += aval * v.x;
                acc.y += aval * v.y;
                acc.z += aval * v.z;
                acc.w += aval * v.w;
            }
        }
    }

    float nn2 = warp_sum(dot4(acc, acc));
    float nn = fmaxf(sqrtf(nn2), EPSF);
    float e = tanhf(nn) / nn;
    float4 ng = make_float4(acc.x * e, acc.y * e, acc.z * e, acc.w * e);

    float4 xv = ((const float4*)x)[(size_t)warp * 32 + lane];
    float nx2 = warp_sum(dot4(xv, xv));
    float ng2 = e * e * nn2;
    float nc = fmaxf(sqrtf(nx2 + ng2), EPSF);
    float s = atanhf(fminf(nc, MAX_TANHF)) / nc;

    float4* C4 = (float4*)g_C;
    C4[(size_t)warp * 64 + lane]      = make_float4(xv.x * s, xv.y * s, xv.z * s, xv.w * s);
    C4[(size_t)warp * 64 + 32 + lane] = make_float4(ng.x * s, ng.y * s, ng.z * s, ng.w * s);
}

// ---------------------------------------------------------------------------
// Stage 3: out = h_add( exp0( C @ layer ), lbias ), K=256 via two 128-chunks
// ---------------------------------------------------------------------------
__global__ void __launch_bounds__(256)
k_g256(const float* __restrict__ A, const float* __restrict__ B,
       const float* __restrict__ lbias, float* __restrict__ out) {
    extern __shared__ char smraw[];
    float* Bs = (float*)smraw;
    ull*   Ap = (ull*)(smraw + BS_BYTES);

    int tid = threadIdx.x, lane = tid & 31, w = tid >> 5;
    int row0 = blockIdx.x * 64;
    const float4* A4 = (const float4*)A;  // row stride 64 float4

    ull acc[4][4];
#pragma unroll
    for (int p = 0; p < 4; p++)
#pragma unroll
        for (int c = 0; c < 4; c++) acc[p][c] = 0ull;

#pragma unroll
    for (int kc = 0; kc < 2; kc++) {
        {
            const float4* B4 = (const float4*)(B + kc * 128 * 128);
            float4* Bs4 = (float4*)Bs;
            for (int i = tid; i < 4096; i += 256) Bs4[i] = B4[i];
        }
        for (int i = tid; i < 32 * 32; i += 256) {
            int pr = i >> 5, cg = i & 31;
            float4 v0 = A4[(size_t)(row0 + 2 * pr) * 64 + kc * 32 + cg];
            float4 v1 = A4[(size_t)(row0 + 2 * pr + 1) * 64 + kc * 32 + cg];
            Ap[(cg * 4 + 0) * SA + pr] = pack2(v0.x, v1.x);
            Ap[(cg * 4 + 1) * SA + pr] = pack2(v0.y, v1.y);
            Ap[(cg * 4 + 2) * SA + pr] = pack2(v0.z, v1.z);
            Ap[(cg * 4 + 3) * SA + pr] = pack2(v0.w, v1.w);
        }
        __syncthreads();
        gemm_mainloop(Bs, Ap, acc, lane, w);
        __syncthreads();
    }

    gemm_epilogue<false>(acc, lbias, out, row0, w, lane);
}

// ---------------------------------------------------------------------------
extern "C" void kernel_launch(void* const* d_in, const int* in_sizes, int n_in,
                              void* d_out, int out_size) {
    const float* x     = (const float*)d_in[0];
    const float* adj   = (const float*)d_in[1];
    const float* embed = (const float*)d_in[2];
    const float* layer = (const float*)d_in[3];
    const float* ebias = (const float*)d_in[4];
    const float* lbias = (const float*)d_in[5];
    float* out = (float*)d_out;

    int N = in_sizes[0] / F;  // 8192

    float *pV, *pC;
    cudaGetSymbolAddress((void**)&pV, g_V);
    cudaGetSymbolAddress((void**)&pC, g_C);

    cudaFuncSetAttribute(k_g128, cudaFuncAttributeMaxDynamicSharedMemorySize, SMEM_G);
    cudaFuncSetAttribute(k_g256, cudaFuncAttributeMaxDynamicSharedMemorySize, SMEM_G);

    k_g128<<<N / 64, 256, SMEM_G>>>(x, embed, ebias, pV);
    k_spmm_fused<<<N / 8, 256>>>(adj, x, N);
    k_g256<<<N / 64, 256, SMEM_G>>>(pC, layer, lbias, out);
}

// round 5
// speedup vs baseline: 1.1333x; 1.1333x over previous
#include <cuda_runtime.h>
#include <math.h>

#define EPSF 1e-7f
#define MAX_TANHF (1.0f - 1e-6f)

constexpr int F = 128;
constexpr int NMAX = 8192;

__device__ float g_V [NMAX * F];      // log0(h)
__device__ float g_C [NMAX * 2 * F];  // log0([x ; neigh])

typedef unsigned long long ull;

__device__ __forceinline__ float warp_sum(float v) {
    v += __shfl_xor_sync(0xffffffffu, v, 16);
    v += __shfl_xor_sync(0xffffffffu, v, 8);
    v += __shfl_xor_sync(0xffffffffu, v, 4);
    v += __shfl_xor_sync(0xffffffffu, v, 2);
    v += __shfl_xor_sync(0xffffffffu, v, 1);
    return v;
}

__device__ __forceinline__ float dot4(float4 a, float4 b) {
    return a.x * b.x + a.y * b.y + a.z * b.z + a.w * b.w;
}

__device__ __forceinline__ void ffma2(ull& d, ull a, ull b) {
    asm("fma.rn.f32x2 %0, %1, %2, %0;" : "+l"(d) : "l"(a), "l"(b));
}
__device__ __forceinline__ ull pack2(float lo, float hi) {
    ull r; asm("mov.b64 %0, {%1, %2};" : "=l"(r) : "f"(lo), "f"(hi)); return r;
}
__device__ __forceinline__ float2 unpack2(ull v) {
    float2 r; asm("mov.b64 {%0, %1}, %2;" : "=f"(r.x), "=f"(r.y) : "l"(v)); return r;
}

// GEMM geometry: 32-row tile, 128 cols, 256 threads (8 warps).
// Warp w owns rows w*4..w*4+3 (= row-pairs 2w, 2w+1); lane owns cols lane*4..+3.
// Per k: LDS.128 B-row slice + broadcast LDS.128 of 2 A-pairs + 8 FFMA2.
// B staged in 32-k chunks (16 KB) so occupancy stays high; A packed for all K.
constexpr int SAP = 18;                       // Ap stride in ull per k (16 pairs + pad, even)
constexpr int BS_CH = 32 * 128;               // floats per B chunk (16 KB)
constexpr int SM1 = BS_CH * 4 + 128 * SAP * 8 + 256;   // ~35 KB
constexpr int SM2 = BS_CH * 4 + 256 * SAP * 8 + 256;   // ~53.5 KB

// Mainloop over one 32-k chunk.
__device__ __forceinline__ void chunk_mainloop(
        const float* __restrict__ Bs, const ull* __restrict__ Ap,
        ull acc[2][4], int lane, int w) {
    const float4* Bs4 = (const float4*)Bs;
#pragma unroll 8
    for (int k = 0; k < 32; k++) {
        float4 b4 = Bs4[k * 32 + lane];
        ull bd0 = pack2(b4.x, b4.x), bd1 = pack2(b4.y, b4.y);
        ull bd2 = pack2(b4.z, b4.z), bd3 = pack2(b4.w, b4.w);
        ulonglong2 a = *(const ulonglong2*)(Ap + k * SAP + 2 * w);
        ffma2(acc[0][0], a.x, bd0); ffma2(acc[0][1], a.x, bd1);
        ffma2(acc[0][2], a.x, bd2); ffma2(acc[0][3], a.x, bd3);
        ffma2(acc[1][0], a.y, bd0); ffma2(acc[1][1], a.y, bd1);
        ffma2(acc[1][2], a.y, bd2); ffma2(acc[1][3], a.y, bd3);
    }
}

// Epilogue: exp0 -> h_add(bias) [-> log0 if DO_LOG]. Warp owns 4 full rows.
template <bool DO_LOG>
__device__ __forceinline__ void gemm_epilogue(
        ull acc[2][4], const float* __restrict__ bias,
        float* __restrict__ Out, int row0, int w, int lane) {
    int c4 = lane * 4;
    float4 bb = *(const float4*)(bias + c4);
    float y2 = warp_sum(dot4(bb, bb));
    float4* O4 = (float4*)Out;
#pragma unroll
    for (int p = 0; p < 2; p++) {
        float2 u0 = unpack2(acc[p][0]), u1 = unpack2(acc[p][1]);
        float2 u2 = unpack2(acc[p][2]), u3 = unpack2(acc[p][3]);
        float4 ur[2] = {make_float4(u0.x, u1.x, u2.x, u3.x),
                        make_float4(u0.y, u1.y, u2.y, u3.y)};
#pragma unroll
        for (int q = 0; q < 2; q++) {
            float4 u = ur[q];
            int row = row0 + w * 4 + 2 * p + q;
            float ne2 = warp_sum(dot4(u, u));
            float ne = fmaxf(sqrtf(ne2), EPSF);
            float sc = tanhf(ne) / ne;
            float4 h = make_float4(u.x * sc, u.y * sc, u.z * sc, u.w * sc);
            float xy = warp_sum(dot4(h, bb));
            float x2 = sc * sc * ne2;
            float c1 = 1.f + 2.f * xy + y2;
            float c2 = 1.f - x2;
            float inv_den = 1.f / fmaxf(1.f + 2.f * xy + x2 * y2, EPSF);
            float4 rr = make_float4((c1 * h.x + c2 * bb.x) * inv_den,
                                    (c1 * h.y + c2 * bb.y) * inv_den,
                                    (c1 * h.z + c2 * bb.z) * inv_den,
                                    (c1 * h.w + c2 * bb.w) * inv_den);
            if (DO_LOG) {
                float nr2 = warp_sum(dot4(rr, rr));
                float nr = fmaxf(sqrtf(nr2), EPSF);
                float s = atanhf(fminf(nr, MAX_TANHF)) / nr;
                rr = make_float4(rr.x * s, rr.y * s, rr.z * s, rr.w * s);
            }
            O4[(size_t)row * 32 + lane] = rr;
        }
    }
}

// ---------------------------------------------------------------------------
// Stage 1: V = log0( h_add( exp0( log0(x) @ embed ), ebias ) )
// ---------------------------------------------------------------------------
__global__ void __launch_bounds__(256)
k_g128(const float* __restrict__ x, const float* __restrict__ B,
       const float* __restrict__ ebias, float* __restrict__ V) {
    extern __shared__ char smraw[];
    float* Bs   = (float*)smraw;                       // 16 KB chunk
    ull*   Ap   = (ull*)(smraw + BS_CH * 4);           // 128*SAP ull
    float* srow = (float*)(smraw + BS_CH * 4 + 128 * SAP * 8);

    int tid = threadIdx.x, lane = tid & 31, w = tid >> 5;
    int row0 = blockIdx.x * 32;
    const float4* X4 = (const float4*)x;

    // per-row log0 scales (warp w: rows w*4..w*4+3)
#pragma unroll
    for (int r = 0; r < 4; r++) {
        int row = w * 4 + r;
        float4 xv = X4[(size_t)(row0 + row) * 32 + lane];
        float n2 = warp_sum(dot4(xv, xv));
        float n = fmaxf(sqrtf(n2), EPSF);
        float sc = atanhf(fminf(n, MAX_TANHF)) / n;
        if (lane == 0) srow[row] = sc;
    }
    __syncthreads();

    // scaled row-pair-packed transpose: Ap[k][pair], 16 pairs, all K=128
    for (int i = tid; i < 16 * 32; i += 256) {
        int pr = i >> 5, cg = i & 31;
        float s0 = srow[2 * pr], s1 = srow[2 * pr + 1];
        float4 v0 = X4[(size_t)(row0 + 2 * pr) * 32 + cg];
        float4 v1 = X4[(size_t)(row0 + 2 * pr + 1) * 32 + cg];
        Ap[(cg * 4 + 0) * SAP + pr] = pack2(v0.x * s0, v1.x * s1);
        Ap[(cg * 4 + 1) * SAP + pr] = pack2(v0.y * s0, v1.y * s1);
        Ap[(cg * 4 + 2) * SAP + pr] = pack2(v0.z * s0, v1.z * s1);
        Ap[(cg * 4 + 3) * SAP + pr] = pack2(v0.w * s0, v1.w * s1);
    }

    ull acc[2][4];
#pragma unroll
    for (int p = 0; p < 2; p++)
#pragma unroll
        for (int c = 0; c < 4; c++) acc[p][c] = 0ull;

#pragma unroll
    for (int kc = 0; kc < 4; kc++) {
        if (kc) __syncthreads();
        const float4* B4 = (const float4*)(B + kc * 32 * 128);
        float4* Bs4 = (float4*)Bs;
        for (int i = tid; i < 1024; i += 256) Bs4[i] = B4[i];
        __syncthreads();
        chunk_mainloop(Bs, Ap + kc * 32 * SAP, acc, lane, w);
    }

    gemm_epilogue<true>(acc, ebias, V, row0, w, lane);
}

// ---------------------------------------------------------------------------
// Stage 2: C = log0([x ; exp0(adj @ V)]) — warp/row, 4-deep rotating prefetch
// ---------------------------------------------------------------------------
__global__ void k_spmm_fused(const float* __restrict__ adj,
                             const float* __restrict__ x, int N) {
    int warp = (blockIdx.x * blockDim.x + threadIdx.x) >> 5;
    int lane = threadIdx.x & 31;
    if (warp >= N) return;

    const float4* V4 = (const float4*)g_V;
    const float4* arow = (const float4*)(adj + (size_t)warp * N);
    float4 acc = make_float4(0.f, 0.f, 0.f, 0.f);

    int nq = N / 4;        // 2048
    int limit = nq - 32;
    float4 buf[4];
#pragma unroll
    for (int d = 0; d < 4; d++) buf[d] = __ldcs(arow + d * 32 + lane);

    for (int jb = 0; jb < nq; jb += 32) {
        int idx = (jb >> 5) & 3;
        float4 cur = buf[idx];
        int nx = jb + 128;
        nx = (nx > limit) ? limit : nx;   // clamped, branchless
        buf[idx] = __ldcs(arow + nx + lane);
#pragma unroll
        for (int c = 0; c < 4; c++) {
            float av = (c == 0) ? cur.x : (c == 1) ? cur.y
                        : (c == 2) ? cur.z : cur.w;
            unsigned m = __ballot_sync(0xffffffffu, av != 0.0f);
            while (m) {
                int b = __ffs(m) - 1;
                m &= m - 1;
                float aval = __shfl_sync(0xffffffffu, av, b);
                int j = (jb + b) * 4 + c;
                float4 v = V4[(size_t)j * 32 + lane];
                acc.x += aval * v.x;
                acc.y += aval * v.y;
                acc.z += aval * v.z;
                acc.w += aval * v.w;
            }
        }
    }

    float nn2 = warp_sum(dot4(acc, acc));
    float nn = fmaxf(sqrtf(nn2), EPSF);
    float e = tanhf(nn) / nn;
    float4 ng = make_float4(acc.x * e, acc.y * e, acc.z * e, acc.w * e);

    float4 xv = ((const float4*)x)[(size_t)warp * 32 + lane];
    float nx2 = warp_sum(dot4(xv, xv));
    float ng2 = e * e * nn2;
    float nc = fmaxf(sqrtf(nx2 + ng2), EPSF);
    float s = atanhf(fminf(nc, MAX_TANHF)) / nc;

    float4* C4 = (float4*)g_C;
    C4[(size_t)warp * 64 + lane]      = make_float4(xv.x * s, xv.y * s, xv.z * s, xv.w * s);
    C4[(size_t)warp * 64 + 32 + lane] = make_float4(ng.x * s, ng.y * s, ng.z * s, ng.w * s);
}

// ---------------------------------------------------------------------------
// Stage 3: out = h_add( exp0( C @ layer ), lbias ), K=256, 8 chunks
// ---------------------------------------------------------------------------
__global__ void __launch_bounds__(256)
k_g256(const float* __restrict__ A, const float* __restrict__ B,
       const float* __restrict__ lbias, float* __restrict__ out) {
    extern __shared__ char smraw[];
    float* Bs = (float*)smraw;
    ull*   Ap = (ull*)(smraw + BS_CH * 4);             // 256*SAP ull

    int tid = threadIdx.x, lane = tid & 31, w = tid >> 5;
    int row0 = blockIdx.x * 32;
    const float4* A4 = (const float4*)A;               // row stride 64 float4

    // row-pair-packed transpose of full K=256
    for (int i = tid; i < 16 * 64; i += 256) {
        int pr = i >> 6, cg = i & 63;
        float4 v0 = A4[(size_t)(row0 + 2 * pr) * 64 + cg];
        float4 v1 = A4[(size_t)(row0 + 2 * pr + 1) * 64 + cg];
        Ap[(cg * 4 + 0) * SAP + pr] = pack2(v0.x, v1.x);
        Ap[(cg * 4 + 1) * SAP + pr] = pack2(v0.y, v1.y);
        Ap[(cg * 4 + 2) * SAP + pr] = pack2(v0.z, v1.z);
        Ap[(cg * 4 + 3) * SAP + pr] = pack2(v0.w, v1.w);
    }

    ull acc[2][4];
#pragma unroll
    for (int p = 0; p < 2; p++)
#pragma unroll
        for (int c = 0; c < 4; c++) acc[p][c] = 0ull;

#pragma unroll
    for (int kc = 0; kc < 8; kc++) {
        if (kc) __syncthreads();
        const float4* B4 = (const float4*)(B + kc * 32 * 128);
        float4* Bs4 = (float4*)Bs;
        for (int i = tid; i < 1024; i += 256) Bs4[i] = B4[i];
        __syncthreads();
        chunk_mainloop(Bs, Ap + kc * 32 * SAP, acc, lane, w);
    }

    gemm_epilogue<false>(acc, lbias, out, row0, w, lane);
}

// ---------------------------------------------------------------------------
extern "C" void kernel_launch(void* const* d_in, const int* in_sizes, int n_in,
                              void* d_out, int out_size) {
    const float* x     = (const float*)d_in[0];
    const float* adj   = (const float*)d_in[1];
    const float* embed = (const float*)d_in[2];
    const float* layer = (const float*)d_in[3];
    const float* ebias = (const float*)d_in[4];
    const float* lbias = (const float*)d_in[5];
    float* out = (float*)d_out;

    int N = in_sizes[0] / F;  // 8192

    float *pV, *pC;
    cudaGetSymbolAddress((void**)&pV, g_V);
    cudaGetSymbolAddress((void**)&pC, g_C);

    cudaFuncSetAttribute(k_g128, cudaFuncAttributeMaxDynamicSharedMemorySize, SM1);
    cudaFuncSetAttribute(k_g256, cudaFuncAttributeMaxDynamicSharedMemorySize, SM2);

    k_g128<<<N / 32, 256, SM1>>>(x, embed, ebias, pV);
    k_spmm_fused<<<N / 8, 256>>>(adj, x, N);
    k_g256<<<N / 32, 256, SM2>>>(pC, layer, lbias, out);
}

// round 6
// speedup vs baseline: 1.2105x; 1.0682x over previous
#include <cuda_runtime.h>
#include <math.h>

#define EPSF 1e-7f
#define MAX_TANHF (1.0f - 1e-6f)

constexpr int F = 128;
constexpr int NMAX = 8192;

__device__ float g_V [NMAX * F];      // log0(h)
__device__ float g_C [NMAX * 2 * F];  // log0([x ; neigh])

__device__ __forceinline__ float warp_sum(float v) {
    v += __shfl_xor_sync(0xffffffffu, v, 16);
    v += __shfl_xor_sync(0xffffffffu, v, 8);
    v += __shfl_xor_sync(0xffffffffu, v, 4);
    v += __shfl_xor_sync(0xffffffffu, v, 2);
    v += __shfl_xor_sync(0xffffffffu, v, 1);
    return v;
}

__device__ __forceinline__ float dot4(float4 a, float4 b) {
    return a.x * b.x + a.y * b.y + a.z * b.z + a.w * b.w;
}

// GEMM geometry: 16-row tile, 256 threads (8 warps), warp owns 2 rows (1 pair),
// lane owns 4 cols. grid = 8192/16 = 512 -> ~3.5 blocks/SM, ~28 warps/SM.
// Per k: broadcast LDS.64 (A pair) + LDS.128 (B slice) + 8 FFMA.
constexpr int SAP2 = 9;          // Ap stride per k in float2 (8 pairs + pad)
constexpr int BS_CH = 32 * 128;  // floats per B chunk (16 KB)
constexpr int SM1 = BS_CH * 4 + 128 * SAP2 * 8 + 256;  // ~26 KB
constexpr int SM2 = BS_CH * 4 + 256 * SAP2 * 8 + 256;  // ~35 KB

__device__ __forceinline__ void chunk_ml(const float4* __restrict__ Bs4,
                                         const float2* __restrict__ Ap2,
                                         float4 acc[2], int lane, int w) {
#pragma unroll
    for (int k = 0; k < 32; k++) {
        float4 b = Bs4[k * 32 + lane];
        float2 a = Ap2[k * SAP2 + w];
        acc[0].x += a.x * b.x; acc[0].y += a.x * b.y;
        acc[0].z += a.x * b.z; acc[0].w += a.x * b.w;
        acc[1].x += a.y * b.x; acc[1].y += a.y * b.y;
        acc[1].z += a.y * b.z; acc[1].w += a.y * b.w;
    }
}

// Epilogue: exp0 -> h_add(bias) [-> log0]. Warp owns 2 full rows.
template <bool DO_LOG>
__device__ __forceinline__ void gemm_epilogue(
        float4 acc[2], const float* __restrict__ bias,
        float* __restrict__ Out, int row0, int w, int lane) {
    int c4 = lane * 4;
    float4 bb = *(const float4*)(bias + c4);
    float y2 = warp_sum(dot4(bb, bb));
    float4* O4 = (float4*)Out;
#pragma unroll
    for (int q = 0; q < 2; q++) {
        float4 u = acc[q];
        int row = row0 + w * 2 + q;
        float ne2 = warp_sum(dot4(u, u));
        float ne = fmaxf(sqrtf(ne2), EPSF);
        float sc = tanhf(ne) / ne;
        float4 h = make_float4(u.x * sc, u.y * sc, u.z * sc, u.w * sc);
        float xy = warp_sum(dot4(h, bb));
        float x2 = sc * sc * ne2;
        float c1 = 1.f + 2.f * xy + y2;
        float c2 = 1.f - x2;
        float inv_den = 1.f / fmaxf(1.f + 2.f * xy + x2 * y2, EPSF);
        float4 rr = make_float4((c1 * h.x + c2 * bb.x) * inv_den,
                                (c1 * h.y + c2 * bb.y) * inv_den,
                                (c1 * h.z + c2 * bb.z) * inv_den,
                                (c1 * h.w + c2 * bb.w) * inv_den);
        if (DO_LOG) {
            float nr2 = warp_sum(dot4(rr, rr));
            float nr = fmaxf(sqrtf(nr2), EPSF);
            float s = atanhf(fminf(nr, MAX_TANHF)) / nr;
            rr = make_float4(rr.x * s, rr.y * s, rr.z * s, rr.w * s);
        }
        O4[(size_t)row * 32 + lane] = rr;
    }
}

// ---------------------------------------------------------------------------
// Stage 1: V = log0( h_add( exp0( log0(x) @ embed ), ebias ) )
// ---------------------------------------------------------------------------
__global__ void __launch_bounds__(256)
k_g128(const float* __restrict__ x, const float* __restrict__ B,
       const float* __restrict__ ebias, float* __restrict__ V) {
    extern __shared__ char smraw[];
    float*  Bs   = (float*)smraw;                          // 16 KB chunk
    float2* Ap2  = (float2*)(smraw + BS_CH * 4);           // 128*SAP2 float2
    float*  srow = (float*)(smraw + BS_CH * 4 + 128 * SAP2 * 8);

    int tid = threadIdx.x, lane = tid & 31, w = tid >> 5;
    int row0 = blockIdx.x * 16;
    const float4* X4 = (const float4*)x;

    // per-row log0 scales (warp w: rows 2w, 2w+1)
#pragma unroll
    for (int r = 0; r < 2; r++) {
        int row = w * 2 + r;
        float4 xv = X4[(size_t)(row0 + row) * 32 + lane];
        float n2 = warp_sum(dot4(xv, xv));
        float n = fmaxf(sqrtf(n2), EPSF);
        float sc = atanhf(fminf(n, MAX_TANHF)) / n;
        if (lane == 0) srow[row] = sc;
    }
    __syncthreads();

    // scaled row-pair transpose: Ap2[k][pair], 8 pairs, all K=128
    {
        int pr = tid >> 5, cg = tid & 31;   // 8 pairs x 32 float4-groups = 256
        float s0 = srow[2 * pr], s1 = srow[2 * pr + 1];
        float4 v0 = X4[(size_t)(row0 + 2 * pr) * 32 + cg];
        float4 v1 = X4[(size_t)(row0 + 2 * pr + 1) * 32 + cg];
        Ap2[(cg * 4 + 0) * SAP2 + pr] = make_float2(v0.x * s0, v1.x * s1);
        Ap2[(cg * 4 + 1) * SAP2 + pr] = make_float2(v0.y * s0, v1.y * s1);
        Ap2[(cg * 4 + 2) * SAP2 + pr] = make_float2(v0.z * s0, v1.z * s1);
        Ap2[(cg * 4 + 3) * SAP2 + pr] = make_float2(v0.w * s0, v1.w * s1);
    }

    float4 acc[2] = {make_float4(0.f, 0.f, 0.f, 0.f),
                     make_float4(0.f, 0.f, 0.f, 0.f)};

#pragma unroll
    for (int kc = 0; kc < 4; kc++) {
        __syncthreads();
        const float4* B4 = (const float4*)(B + kc * BS_CH);
        float4* Bs4w = (float4*)Bs;
        for (int i = tid; i < 1024; i += 256) Bs4w[i] = B4[i];
        __syncthreads();
        chunk_ml((const float4*)Bs, Ap2 + kc * 32 * SAP2, acc, lane, w);
    }

    gemm_epilogue<true>(acc, ebias, V, row0, w, lane);
}

// ---------------------------------------------------------------------------
// Stage 2: C = log0([x ; exp0(adj @ V)]) — R2 body (static double-buffer)
// ---------------------------------------------------------------------------
__global__ void k_spmm_fused(const float* __restrict__ adj,
                             const float* __restrict__ x, int N) {
    int warp = (blockIdx.x * blockDim.x + threadIdx.x) >> 5;
    int lane = threadIdx.x & 31;
    if (warp >= N) return;

    const float4* V4 = (const float4*)g_V;
    const float4* arow = (const float4*)(adj + (size_t)warp * N);
    float4 acc = make_float4(0.f, 0.f, 0.f, 0.f);

    int nq = N / 4;
    float4 a_cur = __ldcs(arow + lane);
    for (int jb = 0; jb < nq; jb += 32) {
        float4 a_nxt = make_float4(0.f, 0.f, 0.f, 0.f);
        if (jb + 32 < nq) a_nxt = __ldcs(arow + jb + 32 + lane);
#pragma unroll
        for (int c = 0; c < 4; c++) {
            float av = (c == 0) ? a_cur.x : (c == 1) ? a_cur.y
                                : (c == 2) ? a_cur.z : a_cur.w;
            unsigned m = __ballot_sync(0xffffffffu, av != 0.0f);
            while (m) {
                int b = __ffs(m) - 1;
                m &= m - 1;
                float aval = __shfl_sync(0xffffffffu, av, b);
                int j = (jb + b) * 4 + c;
                float4 v = V4[(size_t)j * 32 + lane];
                acc.x += aval * v.x;
                acc.y += aval * v.y;
                acc.z += aval * v.z;
                acc.w += aval * v.w;
            }
        }
        a_cur = a_nxt;
    }

    float nn2 = warp_sum(dot4(acc, acc));
    float nn = fmaxf(sqrtf(nn2), EPSF);
    float e = tanhf(nn) / nn;
    float4 ng = make_float4(acc.x * e, acc.y * e, acc.z * e, acc.w * e);

    float4 xv = ((const float4*)x)[(size_t)warp * 32 + lane];
    float nx2 = warp_sum(dot4(xv, xv));
    float ng2 = e * e * nn2;
    float nc = fmaxf(sqrtf(nx2 + ng2), EPSF);
    float s = atanhf(fminf(nc, MAX_TANHF)) / nc;

    float4* C4 = (float4*)g_C;
    C4[(size_t)warp * 64 + lane]      = make_float4(xv.x * s, xv.y * s, xv.z * s, xv.w * s);
    C4[(size_t)warp * 64 + 32 + lane] = make_float4(ng.x * s, ng.y * s, ng.z * s, ng.w * s);
}

// ---------------------------------------------------------------------------
// Stage 3: out = h_add( exp0( C @ layer ), lbias ), K=256 via 8 chunks
// ---------------------------------------------------------------------------
__global__ void __launch_bounds__(256)
k_g256(const float* __restrict__ A, const float* __restrict__ B,
       const float* __restrict__ lbias, float* __restrict__ out) {
    extern __shared__ char smraw[];
    float*  Bs  = (float*)smraw;
    float2* Ap2 = (float2*)(smraw + BS_CH * 4);            // 256*SAP2 float2

    int tid = threadIdx.x, lane = tid & 31, w = tid >> 5;
    int row0 = blockIdx.x * 16;
    const float4* A4 = (const float4*)A;  // row stride 64 float4 (K=256)

    // row-pair transpose of full K=256 (8 pairs x 64 float4-groups = 512)
    for (int i = tid; i < 512; i += 256) {
        int pr = i >> 6, cg = i & 63;
        float4 v0 = A4[(size_t)(row0 + 2 * pr) * 64 + cg];
        float4 v1 = A4[(size_t)(row0 + 2 * pr + 1) * 64 + cg];
        Ap2[(cg * 4 + 0) * SAP2 + pr] = make_float2(v0.x, v1.x);
        Ap2[(cg * 4 + 1) * SAP2 + pr] = make_float2(v0.y, v1.y);
        Ap2[(cg * 4 + 2) * SAP2 + pr] = make_float2(v0.z, v1.z);
        Ap2[(cg * 4 + 3) * SAP2 + pr] = make_float2(v0.w, v1.w);
    }

    float4 acc[2] = {make_float4(0.f, 0.f, 0.f, 0.f),
                     make_float4(0.f, 0.f, 0.f, 0.f)};

#pragma unroll
    for (int kc = 0; kc < 8; kc++) {
        __syncthreads();
        const float4* B4 = (const float4*)(B + kc * BS_CH);
        float4* Bs4w = (float4*)Bs;
        for (int i = tid; i < 1024; i += 256) Bs4w[i] = B4[i];
        __syncthreads();
        chunk_ml((const float4*)Bs, Ap2 + kc * 32 * SAP2, acc, lane, w);
    }

    gemm_epilogue<false>(acc, lbias, out, row0, w, lane);
}

// ---------------------------------------------------------------------------
extern "C" void kernel_launch(void* const* d_in, const int* in_sizes, int n_in,
                              void* d_out, int out_size) {
    const float* x     = (const float*)d_in[0];
    const float* adj   = (const float*)d_in[1];
    const float* embed = (const float*)d_in[2];
    const float* layer = (const float*)d_in[3];
    const float* ebias = (const float*)d_in[4];
    const float* lbias = (const float*)d_in[5];
    float* out = (float*)d_out;

    int N = in_sizes[0] / F;  // 8192

    float *pV, *pC;
    cudaGetSymbolAddress((void**)&pV, g_V);
    cudaGetSymbolAddress((void**)&pC, g_C);

    cudaFuncSetAttribute(k_g128, cudaFuncAttributeMaxDynamicSharedMemorySize, SM1);
    cudaFuncSetAttribute(k_g256, cudaFuncAttributeMaxDynamicSharedMemorySize, SM2);

    k_g128<<<N / 16, 256, SM1>>>(x, embed, ebias, pV);
    k_spmm_fused<<<N / 8, 256>>>(adj, x, N);
    k_g256<<<N / 16, 256, SM2>>>(pC, layer, lbias, out);
}

// round 7
// speedup vs baseline: 1.3471x; 1.1128x over previous
#include <cuda_runtime.h>
#include <cuda_fp16.h>
#include <math.h>

#define EPSF 1e-7f
#define MAX_TANHF (1.0f - 1e-6f)

constexpr int F = 128;
constexpr int NMAX = 8192;

__device__ __half g_Vh[NMAX * F];     // log0(h), fp16 (spmm gather payload)
__device__ float  g_C [NMAX * 2 * F]; // log0([x ; neigh]) fp32

typedef unsigned long long ull;

__device__ __forceinline__ float warp_sum(float v) {
    v += __shfl_xor_sync(0xffffffffu, v, 16);
    v += __shfl_xor_sync(0xffffffffu, v, 8);
    v += __shfl_xor_sync(0xffffffffu, v, 4);
    v += __shfl_xor_sync(0xffffffffu, v, 2);
    v += __shfl_xor_sync(0xffffffffu, v, 1);
    return v;
}

__device__ __forceinline__ float dot4(float4 a, float4 b) {
    return a.x * b.x + a.y * b.y + a.z * b.z + a.w * b.w;
}

__device__ __forceinline__ void ffma2(ull& d, ull a, ull b) {
    asm("fma.rn.f32x2 %0, %1, %2, %0;" : "+l"(d) : "l"(a), "l"(b));
}
__device__ __forceinline__ ull pack2(float lo, float hi) {
    ull r; asm("mov.b64 %0, {%1, %2};" : "=l"(r) : "f"(lo), "f"(hi)); return r;
}
__device__ __forceinline__ float2 unpack2(ull v) {
    float2 r; asm("mov.b64 {%0, %1}, %2;" : "=f"(r.x), "=f"(r.y) : "l"(v)); return r;
}

// GEMM geometry: 32-row tile, 256 threads (8 warps); warp owns 4 rows
// (= row-pairs 2w, 2w+1), lane owns 4 cols. FFMA2 packed accumulators.
// A transposed+row-pair-packed in smem; 2-deep register pipeline on LDS.
constexpr int SAu = 18;  // Ap stride per k in ull (16 pairs + 2 pad, even)

// g128: whole B (64 KB) + Ap for K=128 (18 KB)
constexpr int SM1 = 128 * 128 * 4 + 128 * SAu * 8 + 256;
// g256: 64-k B chunk (32 KB) + Ap for K=256 (36 KB)
constexpr int SM2 = 64 * 128 * 4 + 256 * SAu * 8 + 256;

// 2-deep pipelined mainloop over NK k's (NK = 128 or 64; mask = NK-1).
template <int NK>
__device__ __forceinline__ void mainloop(const float4* __restrict__ Bs4,
                                         const ull* __restrict__ Ap,
                                         ull acc[2][4], int lane, int w) {
    float4 bc = Bs4[lane];
    ulonglong2 ac = *(const ulonglong2*)(Ap + 2 * w);
#pragma unroll 8
    for (int k = 0; k < NK; k++) {
        int kn = (k + 1) & (NK - 1);
        float4 bn = Bs4[kn * 32 + lane];
        ulonglong2 an = *(const ulonglong2*)(Ap + kn * SAu + 2 * w);
        ull bd0 = pack2(bc.x, bc.x), bd1 = pack2(bc.y, bc.y);
        ull bd2 = pack2(bc.z, bc.z), bd3 = pack2(bc.w, bc.w);
        ffma2(acc[0][0], ac.x, bd0); ffma2(acc[0][1], ac.x, bd1);
        ffma2(acc[0][2], ac.x, bd2); ffma2(acc[0][3], ac.x, bd3);
        ffma2(acc[1][0], ac.y, bd0); ffma2(acc[1][1], ac.y, bd1);
        ffma2(acc[1][2], ac.y, bd2); ffma2(acc[1][3], ac.y, bd3);
        bc = bn; ac = an;
    }
}

// Epilogue: exp0 -> h_add(bias) [-> log0 + fp16 store if HALF_OUT].
// Warp owns 4 full rows (2 packed pairs).
template <bool HALF_OUT>
__device__ __forceinline__ void gemm_epilogue(
        ull acc[2][4], const float* __restrict__ bias,
        void* __restrict__ Out, int row0, int w, int lane) {
    int c4 = lane * 4;
    float4 bb = *(const float4*)(bias + c4);
    float y2 = warp_sum(dot4(bb, bb));
#pragma unroll
    for (int p = 0; p < 2; p++) {
        float2 u0 = unpack2(acc[p][0]), u1 = unpack2(acc[p][1]);
        float2 u2 = unpack2(acc[p][2]), u3 = unpack2(acc[p][3]);
        float4 ur[2] = {make_float4(u0.x, u1.x, u2.x, u3.x),
                        make_float4(u0.y, u1.y, u2.y, u3.y)};
#pragma unroll
        for (int q = 0; q < 2; q++) {
            float4 u = ur[q];
            int row = row0 + w * 4 + 2 * p + q;
            float ne2 = warp_sum(dot4(u, u));
            float ne = fmaxf(sqrtf(ne2), EPSF);
            float sc = tanhf(ne) / ne;
            float4 h = make_float4(u.x * sc, u.y * sc, u.z * sc, u.w * sc);
            float xy = warp_sum(dot4(h, bb));
            float x2 = sc * sc * ne2;
            float c1 = 1.f + 2.f * xy + y2;
            float c2 = 1.f - x2;
            float inv_den = 1.f / fmaxf(1.f + 2.f * xy + x2 * y2, EPSF);
            float4 rr = make_float4((c1 * h.x + c2 * bb.x) * inv_den,
                                    (c1 * h.y + c2 * bb.y) * inv_den,
                                    (c1 * h.z + c2 * bb.z) * inv_den,
                                    (c1 * h.w + c2 * bb.w) * inv_den);
            if (HALF_OUT) {
                float nr2 = warp_sum(dot4(rr, rr));
                float nr = fmaxf(sqrtf(nr2), EPSF);
                float s = atanhf(fminf(nr, MAX_TANHF)) / nr;
                half2 p0 = __floats2half2_rn(rr.x * s, rr.y * s);
                half2 p1 = __floats2half2_rn(rr.z * s, rr.w * s);
                uint2 uo;
                uo.x = *reinterpret_cast<unsigned*>(&p0);
                uo.y = *reinterpret_cast<unsigned*>(&p1);
                ((uint2*)Out)[(size_t)row * 32 + lane] = uo;
            } else {
                ((float4*)Out)[(size_t)row * 32 + lane] = rr;
            }
        }
    }
}

// ---------------------------------------------------------------------------
// Stage 1: Vh = fp16( log0( h_add( exp0( log0(x) @ embed ), ebias ) ) )
// ---------------------------------------------------------------------------
__global__ void __launch_bounds__(256)
k_g128(const float* __restrict__ x, const float* __restrict__ B,
       const float* __restrict__ ebias, __half* __restrict__ Vh) {
    extern __shared__ char smraw[];
    float* Bs   = (float*)smraw;                                 // 64 KB
    ull*   Ap   = (ull*)(smraw + 128 * 128 * 4);
    float* srow = (float*)(smraw + 128 * 128 * 4 + 128 * SAu * 8);

    int tid = threadIdx.x, lane = tid & 31, w = tid >> 5;
    int row0 = blockIdx.x * 32;
    const float4* X4 = (const float4*)x;

    // per-row log0 scales (warp w: rows 4w..4w+3)
#pragma unroll
    for (int r = 0; r < 4; r++) {
        int row = w * 4 + r;
        float4 xv = X4[(size_t)(row0 + row) * 32 + lane];
        float n2 = warp_sum(dot4(xv, xv));
        float n = fmaxf(sqrtf(n2), EPSF);
        float sc = atanhf(fminf(n, MAX_TANHF)) / n;
        if (lane == 0) srow[row] = sc;
    }
    {
        const float4* B4 = (const float4*)B;
        float4* Bs4w = (float4*)Bs;
        for (int i = tid; i < 4096; i += 256) Bs4w[i] = B4[i];
    }
    __syncthreads();

    // scaled row-pair transpose: Ap[k][pair], 16 pairs x K=128
    for (int i = tid; i < 512; i += 256) {
        int pr = i >> 5, cg = i & 31;
        float s0 = srow[2 * pr], s1 = srow[2 * pr + 1];
        float4 v0 = X4[(size_t)(row0 + 2 * pr) * 32 + cg];
        float4 v1 = X4[(size_t)(row0 + 2 * pr + 1) * 32 + cg];
        Ap[(cg * 4 + 0) * SAu + pr] = pack2(v0.x * s0, v1.x * s1);
        Ap[(cg * 4 + 1) * SAu + pr] = pack2(v0.y * s0, v1.y * s1);
        Ap[(cg * 4 + 2) * SAu + pr] = pack2(v0.z * s0, v1.z * s1);
        Ap[(cg * 4 + 3) * SAu + pr] = pack2(v0.w * s0, v1.w * s1);
    }
    __syncthreads();

    ull acc[2][4];
#pragma unroll
    for (int p = 0; p < 2; p++)
#pragma unroll
        for (int c = 0; c < 4; c++) acc[p][c] = 0ull;

    mainloop<128>((const float4*)Bs, Ap, acc, lane, w);
    gemm_epilogue<true>(acc, ebias, Vh, row0, w, lane);
}

// ---------------------------------------------------------------------------
// Stage 2: C = log0([x ; exp0(adj @ Vh)]) — warp/row, fp16 gathers (256 B/row)
// ---------------------------------------------------------------------------
__global__ void k_spmm_fused(const float* __restrict__ adj,
                             const float* __restrict__ x,
                             const __half* __restrict__ Vh, int N) {
    int warp = (blockIdx.x * blockDim.x + threadIdx.x) >> 5;
    int lane = threadIdx.x & 31;
    if (warp >= N) return;

    const uint2* V2 = (const uint2*)Vh;   // row = 32 x uint2 (4 halves each)
    const float4* arow = (const float4*)(adj + (size_t)warp * N);
    float4 acc = make_float4(0.f, 0.f, 0.f, 0.f);

    int nq = N / 4;
    float4 a_cur = __ldcs(arow + lane);
    for (int jb = 0; jb < nq; jb += 32) {
        float4 a_nxt = make_float4(0.f, 0.f, 0.f, 0.f);
        if (jb + 32 < nq) a_nxt = __ldcs(arow + jb + 32 + lane);
#pragma unroll
        for (int c = 0; c < 4; c++) {
            float av = (c == 0) ? a_cur.x : (c == 1) ? a_cur.y
                                : (c == 2) ? a_cur.z : a_cur.w;
            unsigned m = __ballot_sync(0xffffffffu, av != 0.0f);
            while (m) {
                int b = __ffs(m) - 1;
                m &= m - 1;
                float aval = __shfl_sync(0xffffffffu, av, b);
                int j = (jb + b) * 4 + c;
                uint2 vr = V2[(size_t)j * 32 + lane];
                half2 h0 = *reinterpret_cast<half2*>(&vr.x);
                half2 h1 = *reinterpret_cast<half2*>(&vr.y);
                float2 f0 = __half22float2(h0);
                float2 f1 = __half22float2(h1);
                acc.x += aval * f0.x;
                acc.y += aval * f0.y;
                acc.z += aval * f1.x;
                acc.w += aval * f1.y;
            }
        }
        a_cur = a_nxt;
    }

    float nn2 = warp_sum(dot4(acc, acc));
    float nn = fmaxf(sqrtf(nn2), EPSF);
    float e = tanhf(nn) / nn;
    float4 ng = make_float4(acc.x * e, acc.y * e, acc.z * e, acc.w * e);

    float4 xv = ((const float4*)x)[(size_t)warp * 32 + lane];
    float nx2 = warp_sum(dot4(xv, xv));
    float ng2 = e * e * nn2;
    float nc = fmaxf(sqrtf(nx2 + ng2), EPSF);
    float s = atanhf(fminf(nc, MAX_TANHF)) / nc;

    float4* C4 = (float4*)g_C;
    C4[(size_t)warp * 64 + lane]      = make_float4(xv.x * s, xv.y * s, xv.z * s, xv.w * s);
    C4[(size_t)warp * 64 + 32 + lane] = make_float4(ng.x * s, ng.y * s, ng.z * s, ng.w * s);
}

// ---------------------------------------------------------------------------
// Stage 3: out = h_add( exp0( C @ layer ), lbias ), K=256 via 4 x 64-k chunks
// ---------------------------------------------------------------------------
__global__ void __launch_bounds__(256)
k_g256(const float* __restrict__ A, const float* __restrict__ B,
       const float* __restrict__ lbias, float* __restrict__ out) {
    extern __shared__ char smraw[];
    float* Bs = (float*)smraw;                         // 32 KB chunk (64 k)
    ull*   Ap = (ull*)(smraw + 64 * 128 * 4);          // 256*SAu ull

    int tid = threadIdx.x, lane = tid & 31, w = tid >> 5;
    int row0 = blockIdx.x * 32;
    const float4* A4 = (const float4*)A;  // row stride 64 float4 (K=256)

    // row-pair transpose of full K=256 (16 pairs x 64 float4-groups)
    for (int i = tid; i < 1024; i += 256) {
        int pr = i >> 6, cg = i & 63;
        float4 v0 = A4[(size_t)(row0 + 2 * pr) * 64 + cg];
        float4 v1 = A4[(size_t)(row0 + 2 * pr + 1) * 64 + cg];
        Ap[(cg * 4 + 0) * SAu + pr] = pack2(v0.x, v1.x);
        Ap[(cg * 4 + 1) * SAu + pr] = pack2(v0.y, v1.y);
        Ap[(cg * 4 + 2) * SAu + pr] = pack2(v0.z, v1.z);
        Ap[(cg * 4 + 3) * SAu + pr] = pack2(v0.w, v1.w);
    }

    ull acc[2][4];
#pragma unroll
    for (int p = 0; p < 2; p++)
#pragma unroll
        for (int c = 0; c < 4; c++) acc[p][c] = 0ull;

#pragma unroll
    for (int kc = 0; kc < 4; kc++) {
        __syncthreads();
        const float4* B4 = (const float4*)(B + kc * 64 * 128);
        float4* Bs4w = (float4*)Bs;
        for (int i = tid; i < 2048; i += 256) Bs4w[i] = B4[i];
        __syncthreads();
        mainloop<64>((const float4*)Bs, Ap + kc * 64 * SAu, acc, lane, w);
    }

    gemm_epilogue<false>(acc, lbias, out, row0, w, lane);
}

// ---------------------------------------------------------------------------
extern "C" void kernel_launch(void* const* d_in, const int* in_sizes, int n_in,
                              void* d_out, int out_size) {
    const float* x     = (const float*)d_in[0];
    const float* adj   = (const float*)d_in[1];
    const float* embed = (const float*)d_in[2];
    const float* layer = (const float*)d_in[3];
    const float* ebias = (const float*)d_in[4];
    const float* lbias = (const float*)d_in[5];
    float* out = (float*)d_out;

    int N = in_sizes[0] / F;  // 8192

    __half* pVh;
    float* pC;
    cudaGetSymbolAddress((void**)&pVh, g_Vh);
    cudaGetSymbolAddress((void**)&pC, g_C);

    cudaFuncSetAttribute(k_g128, cudaFuncAttributeMaxDynamicSharedMemorySize, SM1);
    cudaFuncSetAttribute(k_g256, cudaFuncAttributeMaxDynamicSharedMemorySize, SM2);

    k_g128<<<N / 32, 256, SM1>>>(x, embed, ebias, pVh);
    k_spmm_fused<<<N / 8, 256>>>(adj, x, pVh, N);
    k_g256<<<N / 32, 256, SM2>>>(pC, layer, lbias, out);
}

// round 13
// speedup vs baseline: 1.4365x; 1.0664x over previous
#include <cuda_runtime.h>
#include <cuda_fp16.h>
#include <cuda_bf16.h>
#include <math.h>
#include <stdint.h>

#define EPSF 1e-7f
#define MAX_TANHF (1.0f - 1e-6f)

constexpr int F = 128;
constexpr int NMAX = 8192;
constexpr int TM = 64;    // rows per GEMM block
constexpr int NTH = 128;  // threads per GEMM block

__device__ __half g_Vh[NMAX * F];     // log0(h), fp16 (spmm gather payload)
__device__ float  g_C [NMAX * 2 * F]; // log0([x ; neigh]) fp32

// ---------------------------------------------------------------------------
// helpers
// ---------------------------------------------------------------------------
__device__ __forceinline__ float warp_sum(float v) {
    v += __shfl_xor_sync(0xffffffffu, v, 16);
    v += __shfl_xor_sync(0xffffffffu, v, 8);
    v += __shfl_xor_sync(0xffffffffu, v, 4);
    v += __shfl_xor_sync(0xffffffffu, v, 2);
    v += __shfl_xor_sync(0xffffffffu, v, 1);
    return v;
}
__device__ __forceinline__ float quad_sum(float v) {
    v += __shfl_xor_sync(0xffffffffu, v, 1);
    v += __shfl_xor_sync(0xffffffffu, v, 2);
    return v;
}
__device__ __forceinline__ float dot4(float4 a, float4 b) {
    return a.x * b.x + a.y * b.y + a.z * b.z + a.w * b.w;
}
__device__ __forceinline__ uint32_t bfpk(float a, float b) {
    __nv_bfloat162 t = __floats2bfloat162_rn(a, b);
    return *reinterpret_cast<uint32_t*>(&t);
}
// split 4 floats (ascending k) into bf16x2 hi (8B) + residual lo (8B)
__device__ __forceinline__ void split4(float4 v, uint2& hi, uint2& lo) {
    float h0 = __bfloat162float(__float2bfloat16_rn(v.x));
    float h1 = __bfloat162float(__float2bfloat16_rn(v.y));
    float h2 = __bfloat162float(__float2bfloat16_rn(v.z));
    float h3 = __bfloat162float(__float2bfloat16_rn(v.w));
    hi.x = bfpk(h0, h1); hi.y = bfpk(h2, h3);
    lo.x = bfpk(v.x - h0, v.y - h1); lo.y = bfpk(v.z - h2, v.w - h3);
}
// m16n8k16 row.col bf16 MMA, fp32 accum (sm_80+ PTX; valid on compute_103)
__device__ __forceinline__ void mma_bf(float* c, const uint32_t* a,
                                       uint32_t b0, uint32_t b1) {
    asm volatile("mma.sync.aligned.m16n8k16.row.col.f32.bf16.bf16.f32 "
        "{%0,%1,%2,%3}, {%4,%5,%6,%7}, {%8,%9}, {%0,%1,%2,%3};"
        : "+f"(c[0]), "+f"(c[1]), "+f"(c[2]), "+f"(c[3])
        : "r"(a[0]), "r"(a[1]), "r"(a[2]), "r"(a[3]), "r"(b0), "r"(b1));
}
// h_add coefficients for u (pre-exp0 vector with norm^2 ne2): h = sc*u
__device__ __forceinline__ void hadd_coef(float ne2, float xs, float y2,
                                          float& sc, float& c1, float& c2, float& inv) {
    float ne = fmaxf(sqrtf(ne2), EPSF);
    sc = tanhf(ne) / ne;
    float xy = sc * xs;             // <h, bias>
    float x2 = sc * sc * ne2;       // ||h||^2
    c1 = 1.f + 2.f * xy + y2;
    c2 = 1.f - x2;
    inv = 1.f / fmaxf(1.f + 2.f * xy + x2 * y2, EPSF);
}

// smem layout: bias | srow | Ahi | Alo | Bhi | Blo ; row stride = K*2+16 bytes
__host__ __device__ constexpr int rsK(int K)   { return K * 2 + 16; }
constexpr int SM_BIAS = 0;
constexpr int SM_SROW = 512;
constexpr int SM_AHI  = 1024;
__host__ __device__ constexpr int smAlo(int K) { return SM_AHI + TM * rsK(K); }
__host__ __device__ constexpr int smBhi(int K) { return smAlo(K) + TM * rsK(K); }
__host__ __device__ constexpr int smBlo(int K) { return smBhi(K) + 128 * rsK(K); }
__host__ __device__ constexpr int smTot(int K) { return smBlo(K) + 128 * rsK(K); }

// fill B tiles: Bg is [K][128] row-major fp32 -> smem [n][k] bf16 hi/lo
template <int K>
__device__ __forceinline__ void fill_B(char* sm, const float* __restrict__ Bg, int tid) {
    constexpr int R = rsK(K);
    for (int i = tid; i < 128 * (K / 4); i += NTH) {
        int n = i & 127, k0 = (i >> 7) * 4;   // consecutive tid -> consecutive n (coalesced)
        float4 v = make_float4(Bg[(size_t)(k0 + 0) * 128 + n],
                               Bg[(size_t)(k0 + 1) * 128 + n],
                               Bg[(size_t)(k0 + 2) * 128 + n],
                               Bg[(size_t)(k0 + 3) * 128 + n]);
        uint2 hi, lo;
        split4(v, hi, lo);
        *(uint2*)(sm + smBhi(K) + n * R + k0 * 2) = hi;
        *(uint2*)(sm + smBlo(K) + n * R + k0 * 2) = lo;
    }
}

// bf16-split mainloop: warp computes rows (w*16+g, +8) x 128 cols over K
template <int K>
__device__ __forceinline__ void mma_mainloop(const char* sm, float acc[16][4],
                                             int w, int g, int tig) {
    constexpr int R = rsK(K);
    const char* Ah = sm + SM_AHI   + (w * 16 + g) * R;
    const char* Al = sm + smAlo(K) + (w * 16 + g) * R;
    const char* Bh = sm + smBhi(K) + g * R;
    const char* Bl = sm + smBlo(K) + g * R;
    for (int kt = 0; kt < K / 16; kt++) {
        int kb = (kt * 16 + tig * 2) * 2;   // byte offset of fragment k
        uint32_t ahi[4], alo[4];
        ahi[0] = *(const uint32_t*)(Ah + kb);
        ahi[1] = *(const uint32_t*)(Ah + 8 * R + kb);
        ahi[2] = *(const uint32_t*)(Ah + kb + 16);
        ahi[3] = *(const uint32_t*)(Ah + 8 * R + kb + 16);
        alo[0] = *(const uint32_t*)(Al + kb);
        alo[1] = *(const uint32_t*)(Al + 8 * R + kb);
        alo[2] = *(const uint32_t*)(Al + kb + 16);
        alo[3] = *(const uint32_t*)(Al + 8 * R + kb + 16);
#pragma unroll
        for (int nt = 0; nt < 16; nt++) {
            const char* bh = Bh + nt * 8 * R + kb;
            const char* bl = Bl + nt * 8 * R + kb;
            uint32_t b0 = *(const uint32_t*)(bh);
            uint32_t b1 = *(const uint32_t*)(bh + 16);
            uint32_t l0 = *(const uint32_t*)(bl);
            uint32_t l1 = *(const uint32_t*)(bl + 16);
            mma_bf(acc[nt], ahi, b0, b1);   // hi*hi
            mma_bf(acc[nt], ahi, l0, l1);   // hi*lo
            mma_bf(acc[nt], alo, b0, b1);   // lo*hi
        }
    }
}

// ---------------------------------------------------------------------------
// Stage 1: Vh = fp16( log0( h_add( exp0( log0(x) @ embed ), ebias ) ) )
// ---------------------------------------------------------------------------
__global__ void __launch_bounds__(NTH)
k_mma1(const float* __restrict__ x, const float* __restrict__ Bg,
       const float* __restrict__ ebias, __half* __restrict__ Vh) {
    constexpr int K = 128, R = rsK(128);
    extern __shared__ char sm[];
    int tid = threadIdx.x, lane = tid & 31, w = tid >> 5;
    int g = lane >> 2, tig = lane & 3;
    int row0 = blockIdx.x * TM;

    ((float*)(sm + SM_BIAS))[tid] = ebias[tid];

    // per-row log0 scales
    const float4* X4 = (const float4*)x;
    float* srow = (float*)(sm + SM_SROW);
    for (int rr = 0; rr < 16; rr++) {
        int row = w * 16 + rr;
        float4 xv = X4[(size_t)(row0 + row) * 32 + lane];
        float n2 = warp_sum(dot4(xv, xv));
        float n = fmaxf(sqrtf(n2), EPSF);
        if (lane == 0) srow[row] = atanhf(fminf(n, MAX_TANHF)) / n;
    }
    fill_B<K>(sm, Bg, tid);
    __syncthreads();

    // A fill: scaled log0(x), split
    for (int i = tid; i < TM * 32; i += NTH) {
        int row = i >> 5, cg = i & 31;
        float s = srow[row];
        float4 v = X4[(size_t)(row0 + row) * 32 + cg];
        v.x *= s; v.y *= s; v.z *= s; v.w *= s;
        uint2 hi, lo;
        split4(v, hi, lo);
        *(uint2*)(sm + SM_AHI   + row * R + cg * 8) = hi;
        *(uint2*)(sm + smAlo(K) + row * R + cg * 8) = lo;
    }
    __syncthreads();

    float acc[16][4] = {};
    mma_mainloop<K>(sm, acc, w, g, tig);

    // epilogue: rows r0 = row0+w*16+g, r1 = +8; thread cols nt*8+tig*2+{0,1}
    const float* eb = (const float*)(sm + SM_BIAS);
    float n0 = 0, n1 = 0, xs0 = 0, xs1 = 0, ysp = 0;
#pragma unroll
    for (int nt = 0; nt < 16; nt++) {
        float2 e = *(const float2*)(eb + nt * 8 + tig * 2);
        n0  += acc[nt][0] * acc[nt][0] + acc[nt][1] * acc[nt][1];
        n1  += acc[nt][2] * acc[nt][2] + acc[nt][3] * acc[nt][3];
        xs0 += acc[nt][0] * e.x + acc[nt][1] * e.y;
        xs1 += acc[nt][2] * e.x + acc[nt][3] * e.y;
        ysp += e.x * e.x + e.y * e.y;
    }
    float ne20 = quad_sum(n0), ne21 = quad_sum(n1);
    float xss0 = quad_sum(xs0), xss1 = quad_sum(xs1);
    float y2 = quad_sum(ysp);

    float sc0, c10, c20, iv0, sc1, c11, c21, iv1;
    hadd_coef(ne20, xss0, y2, sc0, c10, c20, iv0);
    hadd_coef(ne21, xss1, y2, sc1, c11, c21, iv1);

    float m0 = 0, m1 = 0;
#pragma unroll
    for (int nt = 0; nt < 16; nt++) {
        float2 e = *(const float2*)(eb + nt * 8 + tig * 2);
        float r00 = (c10 * sc0 * acc[nt][0] + c20 * e.x) * iv0;
        float r01 = (c10 * sc0 * acc[nt][1] + c20 * e.y) * iv0;
        float r10 = (c11 * sc1 * acc[nt][2] + c21 * e.x) * iv1;
        float r11 = (c11 * sc1 * acc[nt][3] + c21 * e.y) * iv1;
        m0 += r00 * r00 + r01 * r01;
        m1 += r10 * r10 + r11 * r11;
        acc[nt][0] = r00; acc[nt][1] = r01; acc[nt][2] = r10; acc[nt][3] = r11;
    }
    float nr0 = fmaxf(sqrtf(quad_sum(m0)), EPSF);
    float nr1 = fmaxf(sqrtf(quad_sum(m1)), EPSF);
    float s0 = atanhf(fminf(nr0, MAX_TANHF)) / nr0;
    float s1 = atanhf(fminf(nr1, MAX_TANHF)) / nr1;

    size_t r0g = (size_t)(row0 + w * 16 + g) * 128;
    size_t r1g = r0g + 8 * 128;
#pragma unroll
    for (int nt = 0; nt < 16; nt++) {
        int col = nt * 8 + tig * 2;
        half2 h0 = __floats2half2_rn(acc[nt][0] * s0, acc[nt][1] * s0);
        half2 h1 = __floats2half2_rn(acc[nt][2] * s1, acc[nt][3] * s1);
        *(uint32_t*)(Vh + r0g + col) = *reinterpret_cast<uint32_t*>(&h0);
        *(uint32_t*)(Vh + r1g + col) = *reinterpret_cast<uint32_t*>(&h1);
    }
}

// ---------------------------------------------------------------------------
// Stage 2: C = log0([x ; exp0(adj @ Vh)]) — warp/row, fp16 gathers (R7 body)
// ---------------------------------------------------------------------------
__global__ void k_spmm_fused(const float* __restrict__ adj,
                             const float* __restrict__ x,
                             const __half* __restrict__ Vh, int N) {
    int warp = (blockIdx.x * blockDim.x + threadIdx.x) >> 5;
    int lane = threadIdx.x & 31;
    if (warp >= N) return;

    const uint2* V2 = (const uint2*)Vh;
    const float4* arow = (const float4*)(adj + (size_t)warp * N);
    float4 acc = make_float4(0.f, 0.f, 0.f, 0.f);

    int nq = N / 4;
    float4 a_cur = __ldcs(arow + lane);
    for (int jb = 0; jb < nq; jb += 32) {
        float4 a_nxt = make_float4(0.f, 0.f, 0.f, 0.f);
        if (jb + 32 < nq) a_nxt = __ldcs(arow + jb + 32 + lane);
#pragma unroll
        for (int c = 0; c < 4; c++) {
            float av = (c == 0) ? a_cur.x : (c == 1) ? a_cur.y
                                : (c == 2) ? a_cur.z : a_cur.w;
            unsigned m = __ballot_sync(0xffffffffu, av != 0.0f);
            while (m) {
                int b = __ffs(m) - 1;
                m &= m - 1;
                float aval = __shfl_sync(0xffffffffu, av, b);
                int j = (jb + b) * 4 + c;
                uint2 vr = V2[(size_t)j * 32 + lane];
                half2 h0 = *reinterpret_cast<half2*>(&vr.x);
                half2 h1 = *reinterpret_cast<half2*>(&vr.y);
                float2 f0 = __half22float2(h0);
                float2 f1 = __half22float2(h1);
                acc.x += aval * f0.x;
                acc.y += aval * f0.y;
                acc.z += aval * f1.x;
                acc.w += aval * f1.y;
            }
        }
        a_cur = a_nxt;
    }

    float nn2 = warp_sum(dot4(acc, acc));
    float nn = fmaxf(sqrtf(nn2), EPSF);
    float e = tanhf(nn) / nn;
    float4 ng = make_float4(acc.x * e, acc.y * e, acc.z * e, acc.w * e);

    float4 xv = ((const float4*)x)[(size_t)warp * 32 + lane];
    float nx2 = warp_sum(dot4(xv, xv));
    float ng2 = e * e * nn2;
    float nc = fmaxf(sqrtf(nx2 + ng2), EPSF);
    float s = atanhf(fminf(nc, MAX_TANHF)) / nc;

    float4* C4 = (float4*)g_C;
    C4[(size_t)warp * 64 + lane]      = make_float4(xv.x * s, xv.y * s, xv.z * s, xv.w * s);
    C4[(size_t)warp * 64 + 32 + lane] = make_float4(ng.x * s, ng.y * s, ng.z * s, ng.w * s);
}

// ---------------------------------------------------------------------------
// Stage 3: out = h_add( exp0( C @ layer ), lbias ), K=256
// ---------------------------------------------------------------------------
__global__ void __launch_bounds__(NTH)
k_mma3(const float* __restrict__ A, const float* __restrict__ Bg,
       const float* __restrict__ lbias, float* __restrict__ out) {
    constexpr int K = 256, R = rsK(256);
    extern __shared__ char sm[];
    int tid = threadIdx.x, lane = tid & 31, w = tid >> 5;
    int g = lane >> 2, tig = lane & 3;
    int row0 = blockIdx.x * TM;

    ((float*)(sm + SM_BIAS))[tid] = lbias[tid];

    fill_B<K>(sm, Bg, tid);
    // A fill: rows of g_C (K=256 -> 64 float4 groups per row)
    const float4* A4 = (const float4*)A;
    for (int i = tid; i < TM * 64; i += NTH) {
        int row = i >> 6, cg = i & 63;
        float4 v = A4[(size_t)(row0 + row) * 64 + cg];
        uint2 hi, lo;
        split4(v, hi, lo);
        *(uint2*)(sm + SM_AHI   + row * R + cg * 8) = hi;
        *(uint2*)(sm + smAlo(K) + row * R + cg * 8) = lo;
    }
    __syncthreads();

    float acc[16][4] = {};
    mma_mainloop<K>(sm, acc, w, g, tig);

    const float* eb = (const float*)(sm + SM_BIAS);
    float n0 = 0, n1 = 0, xs0 = 0, xs1 = 0, ysp = 0;
#pragma unroll
    for (int nt = 0; nt < 16; nt++) {
        float2 e = *(const float2*)(eb + nt * 8 + tig * 2);
        n0  += acc[nt][0] * acc[nt][0] + acc[nt][1] * acc[nt][1];
        n1  += acc[nt][2] * acc[nt][2] + acc[nt][3] * acc[nt][3];
        xs0 += acc[nt][0] * e.x + acc[nt][1] * e.y;
        xs1 += acc[nt][2] * e.x + acc[nt][3] * e.y;
        ysp += e.x * e.x + e.y * e.y;
    }
    float ne20 = quad_sum(n0), ne21 = quad_sum(n1);
    float xss0 = quad_sum(xs0), xss1 = quad_sum(xs1);
    float y2 = quad_sum(ysp);

    float sc0, c10, c20, iv0, sc1, c11, c21, iv1;
    hadd_coef(ne20, xss0, y2, sc0, c10, c20, iv0);
    hadd_coef(ne21, xss1, y2, sc1, c11, c21, iv1);

    size_t r0g = (size_t)(row0 + w * 16 + g) * 128;
    size_t r1g = r0g + 8 * 128;
#pragma unroll
    for (int nt = 0; nt < 16; nt++) {
        int col = nt * 8 + tig * 2;
        float2 e = *(const float2*)(eb + col);
        float2 o0, o1;
        o0.x = (c10 * sc0 * acc[nt][0] + c20 * e.x) * iv0;
        o0.y = (c10 * sc0 * acc[nt][1] + c20 * e.y) * iv0;
        o1.x = (c11 * sc1 * acc[nt][2] + c21 * e.x) * iv1;
        o1.y = (c11 * sc1 * acc[nt][3] + c21 * e.y) * iv1;
        *(float2*)(out + r0g + col) = o0;
        *(float2*)(out + r1g + col) = o1;
    }
}

// ---------------------------------------------------------------------------
extern "C" void kernel_launch(void* const* d_in, const int* in_sizes, int n_in,
                              void* d_out, int out_size) {
    const float* x     = (const float*)d_in[0];
    const float* adj   = (const float*)d_in[1];
    const float* embed = (const float*)d_in[2];
    const float* layer = (const float*)d_in[3];
    const float* ebias = (const float*)d_in[4];
    const float* lbias = (const float*)d_in[5];
    float* out = (float*)d_out;

    int N = in_sizes[0] / F;  // 8192

    __half* pVh;
    float* pC;
    cudaGetSymbolAddress((void**)&pVh, g_Vh);
    cudaGetSymbolAddress((void**)&pC, g_C);

    cudaFuncSetAttribute(k_mma1, cudaFuncAttributeMaxDynamicSharedMemorySize, smTot(128));
    cudaFuncSetAttribute(k_mma3, cudaFuncAttributeMaxDynamicSharedMemorySize, smTot(256));

    k_mma1<<<N / TM, NTH, smTot(128)>>>(x, embed, ebias, pVh);
    k_spmm_fused<<<N / 8, 256>>>(adj, x, pVh, N);
    k_mma3<<<N / TM, NTH, smTot(256)>>>(pC, layer, lbias, out);
}